// round 13
// baseline (speedup 1.0000x reference)
#include <cuda_runtime.h>
#include <cuda_bf16.h>

// LIF neuron scan:
//   u[t] = tau * u[t-1] + x[t];  o[t] = (u[t] > 1);  u[t] *= (1 - o[t])
// x: [B, T, N] fp32, out: [B, T, N] fp32.  B=32, T=32, N=65536.
//
// R13 (= R12 resubmit after infra failure): finer cp.async ring. 4 groups of
// 8 steps through a 3-slot smem ring (48KB), per-thread wait_group only
// (each thread consumes exclusively its own cp.async data -> no
// __syncthreads at all):
//   fire g0,g1,g2 -> wait g0, compute -> fire g3 -> wait g1, compute
//   -> 16-store burst -> wait g2, compute -> wait g3, compute -> 16-store burst
// >=2 groups (256B/thread) in flight through all compute; stores stay pure
// back-to-back 16-deep bursts (R9: ALU between stores costs BW).
// smem 64->48KB + __launch_bounds__(128,4) -> 4 blocks/SM = 16 warps
// (R6's best-measured warp count) with register-free reads (R11's win).

#define T_STEPS 32
#define B_BATCH 32
#define G       8          // steps per cp.async group
#define NSLOT   3          // smem ring slots
#define BLOCK   128

__device__ __forceinline__ void cp_async16(void* smem_dst, const void* gsrc, bool pred) {
    unsigned saddr = (unsigned)__cvta_generic_to_shared(smem_dst);
    if (pred)
        asm volatile("cp.async.cg.shared.global [%0], [%1], 16;\n"
                     :: "r"(saddr), "l"(gsrc));
}
__device__ __forceinline__ void cp_commit() {
    asm volatile("cp.async.commit_group;\n" ::: "memory");
}
template <int N>
__device__ __forceinline__ void cp_wait() {
    asm volatile("cp.async.wait_group %0;\n" :: "n"(N) : "memory");
}

__global__ __launch_bounds__(BLOCK, 4) void lif_scan_kernel(
    const float4* __restrict__ x,
    const float*  __restrict__ tau_p,
    float4*       __restrict__ out,
    int nv,          // N/4 (float4 lanes per (b,t) row)
    int total)       // B * nv
{
    extern __shared__ float4 sbuf[];   // [NSLOT][G][BLOCK] = 48 KB

    int tid = threadIdx.x;
    int i   = blockIdx.x * BLOCK + tid;
    bool active = (i < total);
    int  ii = active ? i : 0;

    // clamp learned decay to [0,1]
    float tau = __ldg(tau_p);
    tau = fminf(fmaxf(tau, 0.0f), 1.0f);

    int b = ii / nv;                   // nv is a power of two; compiler -> shift
    int j = ii - b * nv;

    size_t base = (size_t)b * T_STEPS * nv + j;
    const float4* xb = x   + base;
    float4*       ob = out + base;

    // ---- fire groups 0,1,2 into ring slots 0,1,2 ----
#pragma unroll
    for (int g = 0; g < NSLOT; g++) {
#pragma unroll
        for (int t = 0; t < G; t++)
            cp_async16(&sbuf[(g * G + t) * BLOCK + tid],
                       &xb[(size_t)(g * G + t) * nv], active);
        cp_commit();
    }

    float ux = 0.0f, uy = 0.0f, uz = 0.0f, uw = 0.0f;
    float4 oreg[2 * G];

    // scan G steps from ring slot `slot` into oreg[obase..obase+G)
#define SCAN_GROUP(slot, obase)                                               \
    do {                                                                      \
        _Pragma("unroll")                                                     \
        for (int t = 0; t < G; t++) {                                         \
            float4 xi = sbuf[((slot) * G + t) * BLOCK + tid];                 \
            ux = fmaf(tau, ux, xi.x);                                         \
            uy = fmaf(tau, uy, xi.y);                                         \
            uz = fmaf(tau, uz, xi.z);                                         \
            uw = fmaf(tau, uw, xi.w);                                         \
            float4 o;                                                         \
            o.x = (ux > 1.0f) ? 1.0f : 0.0f;                                  \
            o.y = (uy > 1.0f) ? 1.0f : 0.0f;                                  \
            o.z = (uz > 1.0f) ? 1.0f : 0.0f;                                  \
            o.w = (uw > 1.0f) ? 1.0f : 0.0f;                                  \
            ux = (ux > 1.0f) ? 0.0f : ux;                                     \
            uy = (uy > 1.0f) ? 0.0f : uy;                                     \
            uz = (uz > 1.0f) ? 0.0f : uz;                                     \
            uw = (uw > 1.0f) ? 0.0f : uw;                                     \
            oreg[(obase) + t] = o;                                            \
        }                                                                     \
    } while (0)

    // ---- group 0 ----
    cp_wait<2>();                       // g0 landed (g1,g2 in flight)
    SCAN_GROUP(0, 0);

    // refill slot 0 with group 3 (this thread already consumed its s0 data)
#pragma unroll
    for (int t = 0; t < G; t++)
        cp_async16(&sbuf[t * BLOCK + tid],
                   &xb[(size_t)(3 * G + t) * nv], active);
    cp_commit();

    // ---- group 1 ----
    cp_wait<2>();                       // g1 landed (g2,g3 in flight)
    SCAN_GROUP(1, G);

    // ---- store burst: steps 0..15, pure back-to-back (g2,g3 in flight) ----
    if (active) {
#pragma unroll
        for (int t = 0; t < 2 * G; t++)
            __stcs(&ob[(size_t)t * nv], oreg[t]);
    }

    // ---- group 2 ----
    cp_wait<1>();                       // g2 landed (g3 in flight)
    SCAN_GROUP(2, 0);

    // ---- group 3 (in ring slot 0) ----
    cp_wait<0>();
    SCAN_GROUP(0, G);

    // ---- store burst: steps 16..31 ----
    if (active) {
#pragma unroll
        for (int t = 0; t < 2 * G; t++)
            __stcs(&ob[(size_t)(2 * G + t) * nv], oreg[t]);
    }
#undef SCAN_GROUP
}

extern "C" void kernel_launch(void* const* d_in, const int* in_sizes, int n_in,
                              void* d_out, int out_size)
{
    const float* x   = (const float*)d_in[0];   // [B, T, N] fp32
    const float* tau = (const float*)d_in[1];   // [1] fp32

    int total_elems = in_sizes[0];                       // B*T*N
    int N  = total_elems / (B_BATCH * T_STEPS);
    int nv = N / 4;                                      // float4 per (b,t) row
    int total_threads = B_BATCH * nv;                    // B * nv

    const int smem_bytes = NSLOT * G * BLOCK * (int)sizeof(float4);  // 48 KB

    cudaFuncSetAttribute(lif_scan_kernel,
                         cudaFuncAttributeMaxDynamicSharedMemorySize, smem_bytes);

    int grid = (total_threads + BLOCK - 1) / BLOCK;

    lif_scan_kernel<<<grid, BLOCK, smem_bytes>>>(
        (const float4*)x, tau, (float4*)d_out, nv, total_threads);
}